// round 7
// baseline (speedup 1.0000x reference)
#include <cuda_runtime.h>
#include <cuda_bf16.h>
#include <cstdint>
#include <math.h>

#define BDIM   32
#define TDIM   750
#define FDIM   2048
#define EMBD   2048
#define CDIM   20
#define KTOT   6144
#define MTOT   (BDIM * TDIM)
#define KEASY  150
#define KHARD  37

#define KSPLIT 4
#define TILES_PER_SPLIT (KTOT / 16 / KSPLIT)   // 96

// flat output layout (tuple order: vs, ea, eb, ha, hb, act, cas)
#define OFF_VS   0
#define SZ_VS    (BDIM * CDIM)
#define OFF_EA   (OFF_VS + SZ_VS)
#define SZ_EA    (BDIM * KEASY * EMBD)
#define OFF_EB   (OFF_EA + SZ_EA)
#define OFF_HA   (OFF_EB + SZ_EA)
#define SZ_HA    (BDIM * KHARD * EMBD)
#define OFF_HB   (OFF_HA + SZ_HA)
#define OFF_ACT  (OFF_HB + SZ_HA)
#define OFF_CAS  (OFF_ACT + BDIM * TDIM)

#define IDX_EA 0
#define IDX_EB (BDIM * KEASY)
#define IDX_HA (2 * BDIM * KEASY)
#define IDX_HB (IDX_HA + BDIM * KHARD)

typedef unsigned long long ull;

__device__ float g_Wt[(size_t)KTOT * EMBD];
__device__ float g_part[(size_t)KSPLIT * MTOT * EMBD];   // K-split partial sums
__device__ float g_emb[(size_t)MTOT * EMBD];
__device__ float g_a[MTOT];
__device__ float g_act[MTOT];
__device__ int   g_idx[IDX_HB + BDIM * KHARD];
__device__ float g_vmean[BDIM * CDIM];

// ---------------- f32x2 helpers ----------------
__device__ __forceinline__ ull pack2_dup(float v) {
    ull r; unsigned u = __float_as_uint(v);
    asm("mov.b64 %0, {%1, %2};" : "=l"(r) : "r"(u), "r"(u));
    return r;
}
__device__ __forceinline__ void fma2(ull& c, ull a, ull b) {
    asm("fma.rn.f32x2 %0, %1, %2, %0;" : "+l"(c) : "l"(a), "l"(b));
}
__device__ __forceinline__ void add2(ull& c, ull a) {
    asm("add.rn.f32x2 %0, %0, %1;" : "+l"(c) : "l"(a));
}
__device__ __forceinline__ void unpack2(ull v, float& lo, float& hi) {
    unsigned a, b;
    asm("mov.b64 {%0, %1}, %2;" : "=r"(a), "=r"(b) : "l"(v));
    lo = __uint_as_float(a); hi = __uint_as_float(b);
}

// ---------------- K0: transpose W_embed[e][f][tap] -> g_Wt[k][e], k=tap*2048+f
__global__ void transposeW_kernel(const float* __restrict__ W) {
    __shared__ float tile[32][33];
    const int k0 = blockIdx.x * 32, e0 = blockIdx.y * 32;
    const int tx = threadIdx.x & 31, ty = threadIdx.x >> 5;
    #pragma unroll
    for (int r = ty; r < 32; r += 8) {
        int k = k0 + tx, f = k & 2047, tap = k >> 11;
        tile[r][tx] = W[(size_t)(e0 + r) * KTOT + f * 3 + tap];
    }
    __syncthreads();
    #pragma unroll
    for (int r = ty; r < 32; r += 8)
        g_Wt[(size_t)(k0 + r) * EMBD + e0 + tx] = tile[tx][r];
}

// ---------------- K1: conv-as-GEMM with K-split + 2-level blocked accumulation
// blockIdx.z selects a K range of 1536 (96 tiles of 16). Within: per-tile fresh
// accumulator flushed into the grand accumulator -> near-exact fp32 summation.
__global__ void __launch_bounds__(256) gemm1_kernel(const float* __restrict__ x) {
    __shared__ __align__(16) float As[16][128];
    __shared__ __align__(16) float Bs[16][128];
    const int tid = threadIdx.x;
    const int n0 = blockIdx.x * 128, m0 = blockIdx.y * 128;
    const int kb0 = blockIdx.z * TILES_PER_SPLIT;
    float* __restrict__ partOut = g_part + (size_t)blockIdx.z * MTOT * EMBD;

    const int ar0 = tid >> 2;
    const int ac  = (tid & 3) * 4;
    const int mA0 = m0 + ar0, mA1 = m0 + ar0 + 64;
    const int tA0 = (mA0 < MTOT) ? (mA0 % TDIM) : 0;
    const int tA1 = (mA1 < MTOT) ? (mA1 % TDIM) : 0;
    const bool vm0 = (mA0 < MTOT), vm1 = (mA1 < MTOT);

    const int br = tid >> 5, bc = (tid & 31) * 4;
    const int r0 = (tid >> 4) * 8, c0 = (tid & 15) * 8;

    ull acc[4][8];
    #pragma unroll
    for (int i = 0; i < 4; ++i)
        #pragma unroll
        for (int j = 0; j < 8; ++j) acc[i][j] = 0ull;

    const float4 z4 = make_float4(0.f, 0.f, 0.f, 0.f);
    float4 pa0, pa1, pb0, pb1;

    auto loadG = [&](int kb, float4& a0, float4& a1, float4& b0, float4& b1) {
        int tap = (kb * 16) >> 11;
        int fc  = ((kb * 16) & 2047) + ac;
        int tp0 = tA0 + tap - 1, tp1 = tA1 + tap - 1;
        a0 = (vm0 && (unsigned)tp0 < (unsigned)TDIM)
                 ? *reinterpret_cast<const float4*>(x + (size_t)(mA0 + tap - 1) * FDIM + fc) : z4;
        a1 = (vm1 && (unsigned)tp1 < (unsigned)TDIM)
                 ? *reinterpret_cast<const float4*>(x + (size_t)(mA1 + tap - 1) * FDIM + fc) : z4;
        b0 = *reinterpret_cast<const float4*>(&g_Wt[(size_t)(kb * 16 + br) * EMBD + n0 + bc]);
        b1 = *reinterpret_cast<const float4*>(&g_Wt[(size_t)(kb * 16 + br + 8) * EMBD + n0 + bc]);
    };
    auto toSmem = [&](const float4& a0, const float4& a1, const float4& b0, const float4& b1) {
        As[ac + 0][ar0] = a0.x; As[ac + 1][ar0] = a0.y;
        As[ac + 2][ar0] = a0.z; As[ac + 3][ar0] = a0.w;
        As[ac + 0][ar0 + 64] = a1.x; As[ac + 1][ar0 + 64] = a1.y;
        As[ac + 2][ar0 + 64] = a1.z; As[ac + 3][ar0 + 64] = a1.w;
        *reinterpret_cast<float4*>(&Bs[br][bc])     = b0;
        *reinterpret_cast<float4*>(&Bs[br + 8][bc]) = b1;
    };

    loadG(kb0, pa0, pa1, pb0, pb1);
    toSmem(pa0, pa1, pb0, pb1);
    __syncthreads();

    for (int kb = kb0; kb < kb0 + TILES_PER_SPLIT; ++kb) {
        const bool more = (kb + 1 < kb0 + TILES_PER_SPLIT);
        float4 na0, na1, nb0, nb1;
        if (more) loadG(kb + 1, na0, na1, nb0, nb1);

        // fresh per-tile accumulator
        ull tacc[4][8];
        #pragma unroll
        for (int i = 0; i < 4; ++i)
            #pragma unroll
            for (int j = 0; j < 8; ++j) tacc[i][j] = 0ull;

        #pragma unroll
        for (int k = 0; k < 16; ++k) {
            const ull* ap = reinterpret_cast<const ull*>(&As[k][r0]);
            ull a0 = ap[0], a1 = ap[1], a2 = ap[2], a3 = ap[3];
            float4 q0 = *reinterpret_cast<const float4*>(&Bs[k][c0]);
            float4 q1 = *reinterpret_cast<const float4*>(&Bs[k][c0 + 4]);
            ull bb[8];
            bb[0] = pack2_dup(q0.x); bb[1] = pack2_dup(q0.y);
            bb[2] = pack2_dup(q0.z); bb[3] = pack2_dup(q0.w);
            bb[4] = pack2_dup(q1.x); bb[5] = pack2_dup(q1.y);
            bb[6] = pack2_dup(q1.z); bb[7] = pack2_dup(q1.w);
            #pragma unroll
            for (int j = 0; j < 8; ++j) {
                fma2(tacc[0][j], a0, bb[j]);
                fma2(tacc[1][j], a1, bb[j]);
                fma2(tacc[2][j], a2, bb[j]);
                fma2(tacc[3][j], a3, bb[j]);
            }
        }
        // flush tile into grand accumulator (blocked summation)
        #pragma unroll
        for (int i = 0; i < 4; ++i)
            #pragma unroll
            for (int j = 0; j < 8; ++j) add2(acc[i][j], tacc[i][j]);

        __syncthreads();
        if (more) { toSmem(na0, na1, nb0, nb1); __syncthreads(); }
    }

    // store raw partial sums (no bias/relu here)
    #pragma unroll
    for (int ii = 0; ii < 4; ++ii) {
        float lo[8], hi[8];
        #pragma unroll
        for (int j = 0; j < 8; ++j) unpack2(acc[ii][j], lo[j], hi[j]);
        #pragma unroll
        for (int p = 0; p < 2; ++p) {
            int m = m0 + r0 + ii * 2 + p;
            if (m < MTOT) {
                float4* dst = reinterpret_cast<float4*>(&partOut[(size_t)m * EMBD + n0 + c0]);
                dst[0] = make_float4(p ? hi[0] : lo[0], p ? hi[1] : lo[1],
                                     p ? hi[2] : lo[2], p ? hi[3] : lo[3]);
                dst[1] = make_float4(p ? hi[4] : lo[4], p ? hi[5] : lo[5],
                                     p ? hi[6] : lo[6], p ? hi[7] : lo[7]);
            }
        }
    }
}

// ---------------- K1b: combine partials (ascending k order) + bias + relu ----
__global__ void __launch_bounds__(256) combine_kernel(const float* __restrict__ bE) {
    const size_t N4 = (size_t)MTOT * EMBD / 4;
    size_t i = (size_t)blockIdx.x * 256 + threadIdx.x;
    if (i >= N4) return;
    const size_t STR = (size_t)MTOT * EMBD / 4;
    const float4* P = reinterpret_cast<const float4*>(g_part);
    float4 p0 = P[i], p1 = P[i + STR], p2 = P[i + 2 * STR], p3 = P[i + 3 * STR];
    int e = (int)((i * 4) & (EMBD - 1));
    float4 b = *reinterpret_cast<const float4*>(bE + e);
    float4 o;
    o.x = fmaxf(__fadd_rn(__fadd_rn(__fadd_rn(__fadd_rn(p0.x, p1.x), p2.x), p3.x), b.x), 0.f);
    o.y = fmaxf(__fadd_rn(__fadd_rn(__fadd_rn(__fadd_rn(p0.y, p1.y), p2.y), p3.y), b.y), 0.f);
    o.z = fmaxf(__fadd_rn(__fadd_rn(__fadd_rn(__fadd_rn(p0.z, p1.z), p2.z), p3.z), b.z), 0.f);
    o.w = fmaxf(__fadd_rn(__fadd_rn(__fadd_rn(__fadd_rn(p0.w, p1.w), p2.w), p3.w), b.w), 0.f);
    reinterpret_cast<float4*>(g_emb)[i] = o;
}

// ---------------- K2: classifier (smem weights, tree reduce) + actionness ----
__global__ void __launch_bounds__(256) cas_kernel(const float* __restrict__ Wcls,
                                                  const float* __restrict__ bcls,
                                                  float* __restrict__ casOut) {
    __shared__ float Ws[512][21];
    const int tid = threadIdx.x, lane = tid & 31, warp = tid >> 5;
    const int row = blockIdx.x * 8 + warp;

    float acc[CDIM];
    #pragma unroll
    for (int c = 0; c < CDIM; ++c) acc[c] = 0.f;

    for (int ch = 0; ch < 4; ++ch) {
        __syncthreads();
        for (int idx = tid; idx < 512 * CDIM; idx += 256) {
            int c = idx >> 9, e = idx & 511;
            Ws[e][c] = Wcls[c * EMBD + ch * 512 + e];
        }
        __syncthreads();
        const float* er = g_emb + (size_t)row * EMBD + ch * 512;
        #pragma unroll 4
        for (int eb = 0; eb < 512; eb += 32) {
            float v = er[eb + lane];
            const float* wr = &Ws[eb + lane][0];
            #pragma unroll
            for (int c = 0; c < CDIM; ++c) acc[c] = fmaf(v, wr[c], acc[c]);
        }
    }

    double dtot = 0.0;
    float mine = 0.f;
    #pragma unroll
    for (int c = 0; c < CDIM; ++c) {
        float s = acc[c];
        #pragma unroll
        for (int o = 16; o; o >>= 1) s += __shfl_xor_sync(0xffffffffu, s, o);
        float val = __fadd_rn(s, bcls[c]);    // cas value incl. bias
        if (lane == c) mine = val;
        dtot += (double)val;                  // exact class-sum
    }

    if (lane < CDIM) casOut[row * CDIM + lane] = mine;
    if (lane == 0)   g_a[row] = (float)dtot;
}

// ---------------- K3: circular smoothing (double internal) ----------------
__global__ void smooth_kernel(float* __restrict__ actOut) {
    const int b = blockIdx.x, t = threadIdx.x;
    __shared__ float a[TDIM];
    if (t < TDIM) a[t] = g_a[b * TDIM + t];
    __syncthreads();
    if (t < TDIM) {
        int p1 = (t + 1) % TDIM,  m1 = (t + TDIM - 1) % TDIM;
        int p2 = (t + 2) % TDIM,  m2 = (t + TDIM - 2) % TDIM;
        double v = (double)a[t]
                 + 0.1  * (double)a[p1] + 0.1  * (double)a[m1]
                 + 0.02 * (double)a[p2] + 0.02 * (double)a[m2];
        float vf = (float)v;
        g_act[b * TDIM + t]  = vf;
        actOut[b * TDIM + t] = vf;
    }
}

// ---------------- bitonic sorts (blockDim = 1024) ----------------
__device__ void bitonic_f(float* d, int tid, bool desc) {
    for (int k = 2; k <= 1024; k <<= 1)
        for (int j = k >> 1; j > 0; j >>= 1) {
            int x = tid ^ j;
            if (x > tid) {
                float a = d[tid], b = d[x];
                bool up = ((tid & k) == 0) != desc;
                if (up ? (a > b) : (a < b)) { d[tid] = b; d[x] = a; }
            }
            __syncthreads();
        }
}
__device__ void bitonic_u64_desc(ull* d, int tid) {
    for (int k = 2; k <= 1024; k <<= 1)
        for (int j = k >> 1; j > 0; j >>= 1) {
            int x = tid ^ j;
            if (x > tid) {
                ull a = d[tid], b = d[x];
                bool up = ((tid & k) == 0);
                if (up ? (a < b) : (a > b)) { d[tid] = b; d[x] = a; }
            }
            __syncthreads();
        }
}

// ---------------- K4: per-batch median/max/morphology + 4 index top-ks ----
__global__ void __launch_bounds__(1024) stats_topk_kernel() {
    const int b = blockIdx.x, tid = threadIdx.x;
    __shared__ float act[TDIM];
    __shared__ float abin[TDIM];
    __shared__ float sv[1024];
    __shared__ ull   keys[1024];
    __shared__ float scal[2];

    const float NI = __int_as_float(0xff800000);
    const float PI = __int_as_float(0x7f800000);

    if (tid < TDIM) act[tid] = g_act[b * TDIM + tid];
    __syncthreads();

    sv[tid] = (tid < TDIM) ? act[tid] : NI;
    __syncthreads();
    for (int s = 512; s > 0; s >>= 1) {
        if (tid < s) sv[tid] = fmaxf(sv[tid], sv[tid + s]);
        __syncthreads();
    }
    if (tid == 0) scal[0] = sv[0];
    __syncthreads();

    sv[tid] = (tid < TDIM) ? act[tid] : PI;
    __syncthreads();
    bitonic_f(sv, tid, false);
    if (tid == 0)
        scal[1] = __fmul_rn(0.5f, __fadd_rn(sv[374], sv[375]));
    __syncthreads();

    const float amax = scal[0], med = scal[1];
    if (tid < TDIM) abin[tid] = (act[tid] > med) ? 1.f : 0.f;
    __syncthreads();

    float sc[4] = {0.f, 0.f, 0.f, 0.f};
    if (tid < TDIM) {
        const int t = tid;
        const float a = act[t];
        float e3 = (t >= 1 && t <= TDIM - 2)
                       ? fminf(fminf(abin[t - 1], abin[t]), abin[t + 1]) : 0.f;
        float e6 = 0.f;
        if (t >= 3 && t <= TDIM - 3) {
            e6 = fminf(fminf(fminf(abin[t - 3], abin[t - 2]), fminf(abin[t - 1], abin[t])),
                       fminf(abin[t + 1], abin[t + 2]));
        }
        float d3 = abin[t];
        if (t >= 1)        d3 = fmaxf(d3, abin[t - 1]);
        if (t <= TDIM - 2) d3 = fmaxf(d3, abin[t + 1]);
        float d6 = abin[t];
        if (t >= 1)        d6 = fmaxf(d6, abin[t - 1]);
        if (t >= 2)        d6 = fmaxf(d6, abin[t - 2]);
        if (t <= TDIM - 2) d6 = fmaxf(d6, abin[t + 1]);
        if (t <= TDIM - 3) d6 = fmaxf(d6, abin[t + 2]);
        if (t <= TDIM - 4) d6 = fmaxf(d6, abin[t + 3]);

        sc[0] = a;
        sc[1] = __fsub_rn(amax, a);
        sc[2] = __fmul_rn(a, __fsub_rn(e3, e6));
        sc[3] = __fmul_rn(a, __fsub_rn(d6, d3));
    }

    const int kk[4]  = {KEASY, KEASY, KHARD, KHARD};
    const int off[4] = {IDX_EA, IDX_EB, IDX_HA, IDX_HB};
    for (int pass = 0; pass < 4; ++pass) {
        __syncthreads();
        ull key = 0ull;
        if (tid < TDIM) {
            unsigned u = __float_as_uint(sc[pass]);
            u = (u & 0x80000000u) ? ~u : (u | 0x80000000u);
            key = ((ull)u << 32) | (ull)(0xFFFFFFFFu - (unsigned)tid);
        }
        keys[tid] = key;
        __syncthreads();
        bitonic_u64_desc(keys, tid);
        if (tid < kk[pass]) {
            unsigned idx = 0xFFFFFFFFu - (unsigned)(keys[tid] & 0xFFFFFFFFull);
            g_idx[off[pass] + b * kk[pass] + tid] = (int)idx;
        }
    }
}

// ---------------- K5: per-(b,c) top-150 mean of cas over time ----------------
__global__ void __launch_bounds__(1024) classtopk_kernel(const float* __restrict__ cas) {
    const int bc = blockIdx.x;
    const int b = bc / CDIM, c = bc % CDIM;
    const int tid = threadIdx.x;
    __shared__ float sv[1024];
    sv[tid] = (tid < TDIM) ? cas[(b * TDIM + tid) * CDIM + c] : __int_as_float(0xff800000);
    __syncthreads();
    bitonic_f(sv, tid, true);
    if (tid == 0) {
        float s = 0.f;
        for (int i = 0; i < KEASY; ++i) s = __fadd_rn(s, sv[i]);
        g_vmean[bc] = s / (float)KEASY;
    }
}

// ---------------- K6: softmax over classes ----------------
__global__ void softmax_kernel(float* __restrict__ vs) {
    const int lane = threadIdx.x & 31, w = threadIdx.x >> 5;
    if (w >= BDIM) return;
    float v = (lane < CDIM) ? g_vmean[w * CDIM + lane] : __int_as_float(0xff800000);
    float m = v;
    #pragma unroll
    for (int o = 16; o; o >>= 1) m = fmaxf(m, __shfl_xor_sync(0xffffffffu, m, o));
    float e = (lane < CDIM) ? expf(v - m) : 0.f;
    float s = e;
    #pragma unroll
    for (int o = 16; o; o >>= 1) s += __shfl_xor_sync(0xffffffffu, s, o);
    if (lane < CDIM) vs[w * CDIM + lane] = e / s;
}

// ---------------- K7: gather selected embedding rows ----------------
__global__ void __launch_bounds__(256) gather_kernel(const int* __restrict__ idx,
                                                     int k, float* __restrict__ dst) {
    const int r = blockIdx.x;
    const int b = r / k;
    const int t = idx[r];
    const float4* src = reinterpret_cast<const float4*>(
        g_emb + (size_t)(b * TDIM + t) * EMBD);
    float4* out = reinterpret_cast<float4*>(dst + (size_t)r * EMBD);
    #pragma unroll
    for (int i = 0; i < 2; ++i)
        out[threadIdx.x + 256 * i] = src[threadIdx.x + 256 * i];
}

// ---------------- launcher ----------------
extern "C" void kernel_launch(void* const* d_in, const int* in_sizes, int n_in,
                              void* d_out, int out_size) {
    (void)in_sizes; (void)n_in; (void)out_size;
    const float* x       = (const float*)d_in[0];
    const float* W_embed = (const float*)d_in[1];
    const float* b_embed = (const float*)d_in[2];
    const float* W_cls   = (const float*)d_in[3];
    const float* b_cls   = (const float*)d_in[4];
    float* out = (float*)d_out;

    int* idxp;
    cudaGetSymbolAddress((void**)&idxp, g_idx);

    transposeW_kernel<<<dim3(KTOT / 32, EMBD / 32), 256>>>(W_embed);
    gemm1_kernel<<<dim3(EMBD / 128, (MTOT + 127) / 128, KSPLIT), 256>>>(x);
    {
        size_t n4 = (size_t)MTOT * EMBD / 4;
        combine_kernel<<<(unsigned)((n4 + 255) / 256), 256>>>(b_embed);
    }
    cas_kernel<<<MTOT / 8, 256>>>(W_cls, b_cls, out + OFF_CAS);
    smooth_kernel<<<BDIM, 768>>>(out + OFF_ACT);
    stats_topk_kernel<<<BDIM, 1024>>>();
    classtopk_kernel<<<BDIM * CDIM, 1024>>>(out + OFF_CAS);
    softmax_kernel<<<1, 1024>>>(out + OFF_VS);
    gather_kernel<<<BDIM * KEASY, 256>>>(idxp + IDX_EA, KEASY, out + OFF_EA);
    gather_kernel<<<BDIM * KEASY, 256>>>(idxp + IDX_EB, KEASY, out + OFF_EB);
    gather_kernel<<<BDIM * KHARD, 256>>>(idxp + IDX_HA, KHARD, out + OFF_HA);
    gather_kernel<<<BDIM * KHARD, 256>>>(idxp + IDX_HB, KHARD, out + OFF_HB);
}

// round 8
// speedup vs baseline: 1.0010x; 1.0010x over previous
#include <cuda_runtime.h>
#include <cuda_bf16.h>
#include <cstdint>
#include <math.h>

#define BDIM   32
#define TDIM   750
#define FDIM   2048
#define EMBD   2048
#define CDIM   20
#define KTOT   6144
#define MTOT   (BDIM * TDIM)
#define KEASY  150
#define KHARD  37

#define KSPLIT 4
#define TILES_PER_SPLIT (KTOT / 16 / KSPLIT)   // 96

// flat output layout (tuple order: vs, ea, eb, ha, hb, act, cas)
#define OFF_VS   0
#define SZ_VS    (BDIM * CDIM)
#define OFF_EA   (OFF_VS + SZ_VS)
#define SZ_EA    (BDIM * KEASY * EMBD)
#define OFF_EB   (OFF_EA + SZ_EA)
#define OFF_HA   (OFF_EB + SZ_EA)
#define SZ_HA    (BDIM * KHARD * EMBD)
#define OFF_HB   (OFF_HA + SZ_HA)
#define OFF_ACT  (OFF_HB + SZ_HA)
#define OFF_CAS  (OFF_ACT + BDIM * TDIM)

#define IDX_EA 0
#define IDX_EB (BDIM * KEASY)
#define IDX_HA (2 * BDIM * KEASY)
#define IDX_HB (IDX_HA + BDIM * KHARD)

typedef unsigned long long ull;

__device__ float g_Wt[(size_t)KTOT * EMBD];
__device__ float g_part[(size_t)KSPLIT * MTOT * EMBD];   // K-split partial sums
__device__ float g_emb[(size_t)MTOT * EMBD];
__device__ float g_a[MTOT];
__device__ float g_act[MTOT];
__device__ int   g_idx[IDX_HB + BDIM * KHARD];
__device__ float g_vmean[BDIM * CDIM];

// ---------------- f32x2 helpers ----------------
__device__ __forceinline__ ull pack2_dup(float v) {
    ull r; unsigned u = __float_as_uint(v);
    asm("mov.b64 %0, {%1, %2};" : "=l"(r) : "r"(u), "r"(u));
    return r;
}
__device__ __forceinline__ void fma2(ull& c, ull a, ull b) {
    asm("fma.rn.f32x2 %0, %1, %2, %0;" : "+l"(c) : "l"(a), "l"(b));
}
__device__ __forceinline__ void add2(ull& c, ull a) {
    asm("add.rn.f32x2 %0, %0, %1;" : "+l"(c) : "l"(a));
}
__device__ __forceinline__ void unpack2(ull v, float& lo, float& hi) {
    unsigned a, b;
    asm("mov.b64 {%0, %1}, %2;" : "=r"(a), "=r"(b) : "l"(v));
    lo = __uint_as_float(a); hi = __uint_as_float(b);
}

// ---------------- K0: transpose W_embed[e][f][tap] -> g_Wt[k][e], k=tap*2048+f
__global__ void transposeW_kernel(const float* __restrict__ W) {
    __shared__ float tile[32][33];
    const int k0 = blockIdx.x * 32, e0 = blockIdx.y * 32;
    const int tx = threadIdx.x & 31, ty = threadIdx.x >> 5;
    #pragma unroll
    for (int r = ty; r < 32; r += 8) {
        int k = k0 + tx, f = k & 2047, tap = k >> 11;
        tile[r][tx] = W[(size_t)(e0 + r) * KTOT + f * 3 + tap];
    }
    __syncthreads();
    #pragma unroll
    for (int r = ty; r < 32; r += 8)
        g_Wt[(size_t)(k0 + r) * EMBD + e0 + tx] = tile[tx][r];
}

// ---------------- K1: conv-as-GEMM with K-split + 2-level blocked accumulation
// blockIdx.z selects a K range of 1536 (96 tiles of 16). Within: per-tile fresh
// accumulator flushed into the grand accumulator -> near-exact fp32 summation.
__global__ void __launch_bounds__(256) gemm1_kernel(const float* __restrict__ x) {
    __shared__ __align__(16) float As[16][128];
    __shared__ __align__(16) float Bs[16][128];
    const int tid = threadIdx.x;
    const int n0 = blockIdx.x * 128, m0 = blockIdx.y * 128;
    const int kb0 = blockIdx.z * TILES_PER_SPLIT;
    float* __restrict__ partOut = g_part + (size_t)blockIdx.z * MTOT * EMBD;

    const int ar0 = tid >> 2;
    const int ac  = (tid & 3) * 4;
    const int mA0 = m0 + ar0, mA1 = m0 + ar0 + 64;
    const int tA0 = (mA0 < MTOT) ? (mA0 % TDIM) : 0;
    const int tA1 = (mA1 < MTOT) ? (mA1 % TDIM) : 0;
    const bool vm0 = (mA0 < MTOT), vm1 = (mA1 < MTOT);

    const int br = tid >> 5, bc = (tid & 31) * 4;
    const int r0 = (tid >> 4) * 8, c0 = (tid & 15) * 8;

    ull acc[4][8];
    #pragma unroll
    for (int i = 0; i < 4; ++i)
        #pragma unroll
        for (int j = 0; j < 8; ++j) acc[i][j] = 0ull;

    const float4 z4 = make_float4(0.f, 0.f, 0.f, 0.f);
    float4 pa0, pa1, pb0, pb1;

    auto loadG = [&](int kb, float4& a0, float4& a1, float4& b0, float4& b1) {
        int tap = (kb * 16) >> 11;
        int fc  = ((kb * 16) & 2047) + ac;
        int tp0 = tA0 + tap - 1, tp1 = tA1 + tap - 1;
        a0 = (vm0 && (unsigned)tp0 < (unsigned)TDIM)
                 ? *reinterpret_cast<const float4*>(x + (size_t)(mA0 + tap - 1) * FDIM + fc) : z4;
        a1 = (vm1 && (unsigned)tp1 < (unsigned)TDIM)
                 ? *reinterpret_cast<const float4*>(x + (size_t)(mA1 + tap - 1) * FDIM + fc) : z4;
        b0 = *reinterpret_cast<const float4*>(&g_Wt[(size_t)(kb * 16 + br) * EMBD + n0 + bc]);
        b1 = *reinterpret_cast<const float4*>(&g_Wt[(size_t)(kb * 16 + br + 8) * EMBD + n0 + bc]);
    };
    auto toSmem = [&](const float4& a0, const float4& a1, const float4& b0, const float4& b1) {
        As[ac + 0][ar0] = a0.x; As[ac + 1][ar0] = a0.y;
        As[ac + 2][ar0] = a0.z; As[ac + 3][ar0] = a0.w;
        As[ac + 0][ar0 + 64] = a1.x; As[ac + 1][ar0 + 64] = a1.y;
        As[ac + 2][ar0 + 64] = a1.z; As[ac + 3][ar0 + 64] = a1.w;
        *reinterpret_cast<float4*>(&Bs[br][bc])     = b0;
        *reinterpret_cast<float4*>(&Bs[br + 8][bc]) = b1;
    };

    loadG(kb0, pa0, pa1, pb0, pb1);
    toSmem(pa0, pa1, pb0, pb1);
    __syncthreads();

    for (int kb = kb0; kb < kb0 + TILES_PER_SPLIT; ++kb) {
        const bool more = (kb + 1 < kb0 + TILES_PER_SPLIT);
        float4 na0, na1, nb0, nb1;
        if (more) loadG(kb + 1, na0, na1, nb0, nb1);

        // fresh per-tile accumulator
        ull tacc[4][8];
        #pragma unroll
        for (int i = 0; i < 4; ++i)
            #pragma unroll
            for (int j = 0; j < 8; ++j) tacc[i][j] = 0ull;

        #pragma unroll
        for (int k = 0; k < 16; ++k) {
            const ull* ap = reinterpret_cast<const ull*>(&As[k][r0]);
            ull a0 = ap[0], a1 = ap[1], a2 = ap[2], a3 = ap[3];
            float4 q0 = *reinterpret_cast<const float4*>(&Bs[k][c0]);
            float4 q1 = *reinterpret_cast<const float4*>(&Bs[k][c0 + 4]);
            ull bb[8];
            bb[0] = pack2_dup(q0.x); bb[1] = pack2_dup(q0.y);
            bb[2] = pack2_dup(q0.z); bb[3] = pack2_dup(q0.w);
            bb[4] = pack2_dup(q1.x); bb[5] = pack2_dup(q1.y);
            bb[6] = pack2_dup(q1.z); bb[7] = pack2_dup(q1.w);
            #pragma unroll
            for (int j = 0; j < 8; ++j) {
                fma2(tacc[0][j], a0, bb[j]);
                fma2(tacc[1][j], a1, bb[j]);
                fma2(tacc[2][j], a2, bb[j]);
                fma2(tacc[3][j], a3, bb[j]);
            }
        }
        // flush tile into grand accumulator (blocked summation)
        #pragma unroll
        for (int i = 0; i < 4; ++i)
            #pragma unroll
            for (int j = 0; j < 8; ++j) add2(acc[i][j], tacc[i][j]);

        __syncthreads();
        if (more) { toSmem(na0, na1, nb0, nb1); __syncthreads(); }
    }

    // store raw partial sums (no bias/relu here)
    #pragma unroll
    for (int ii = 0; ii < 4; ++ii) {
        float lo[8], hi[8];
        #pragma unroll
        for (int j = 0; j < 8; ++j) unpack2(acc[ii][j], lo[j], hi[j]);
        #pragma unroll
        for (int p = 0; p < 2; ++p) {
            int m = m0 + r0 + ii * 2 + p;
            if (m < MTOT) {
                float4* dst = reinterpret_cast<float4*>(&partOut[(size_t)m * EMBD + n0 + c0]);
                dst[0] = make_float4(p ? hi[0] : lo[0], p ? hi[1] : lo[1],
                                     p ? hi[2] : lo[2], p ? hi[3] : lo[3]);
                dst[1] = make_float4(p ? hi[4] : lo[4], p ? hi[5] : lo[5],
                                     p ? hi[6] : lo[6], p ? hi[7] : lo[7]);
            }
        }
    }
}

// ---------------- K1b: combine partials (ascending k order) + bias + relu ----
__global__ void __launch_bounds__(256) combine_kernel(const float* __restrict__ bE) {
    const size_t N4 = (size_t)MTOT * EMBD / 4;
    size_t i = (size_t)blockIdx.x * 256 + threadIdx.x;
    if (i >= N4) return;
    const size_t STR = (size_t)MTOT * EMBD / 4;
    const float4* P = reinterpret_cast<const float4*>(g_part);
    float4 p0 = P[i], p1 = P[i + STR], p2 = P[i + 2 * STR], p3 = P[i + 3 * STR];
    int e = (int)((i * 4) & (EMBD - 1));
    float4 b = *reinterpret_cast<const float4*>(bE + e);
    float4 o;
    o.x = fmaxf(__fadd_rn(__fadd_rn(__fadd_rn(__fadd_rn(p0.x, p1.x), p2.x), p3.x), b.x), 0.f);
    o.y = fmaxf(__fadd_rn(__fadd_rn(__fadd_rn(__fadd_rn(p0.y, p1.y), p2.y), p3.y), b.y), 0.f);
    o.z = fmaxf(__fadd_rn(__fadd_rn(__fadd_rn(__fadd_rn(p0.z, p1.z), p2.z), p3.z), b.z), 0.f);
    o.w = fmaxf(__fadd_rn(__fadd_rn(__fadd_rn(__fadd_rn(p0.w, p1.w), p2.w), p3.w), b.w), 0.f);
    reinterpret_cast<float4*>(g_emb)[i] = o;
}

// ---------------- K2: classifier (smem weights, tree reduce) + actionness ----
__global__ void __launch_bounds__(256) cas_kernel(const float* __restrict__ Wcls,
                                                  const float* __restrict__ bcls,
                                                  float* __restrict__ casOut) {
    __shared__ float Ws[512][21];
    const int tid = threadIdx.x, lane = tid & 31, warp = tid >> 5;
    const int row = blockIdx.x * 8 + warp;

    float acc[CDIM];
    #pragma unroll
    for (int c = 0; c < CDIM; ++c) acc[c] = 0.f;

    for (int ch = 0; ch < 4; ++ch) {
        __syncthreads();
        for (int idx = tid; idx < 512 * CDIM; idx += 256) {
            int c = idx >> 9, e = idx & 511;
            Ws[e][c] = Wcls[c * EMBD + ch * 512 + e];
        }
        __syncthreads();
        const float* er = g_emb + (size_t)row * EMBD + ch * 512;
        #pragma unroll 4
        for (int eb = 0; eb < 512; eb += 32) {
            float v = er[eb + lane];
            const float* wr = &Ws[eb + lane][0];
            #pragma unroll
            for (int c = 0; c < CDIM; ++c) acc[c] = fmaf(v, wr[c], acc[c]);
        }
    }

    double dtot = 0.0;
    float mine = 0.f;
    #pragma unroll
    for (int c = 0; c < CDIM; ++c) {
        float s = acc[c];
        #pragma unroll
        for (int o = 16; o; o >>= 1) s += __shfl_xor_sync(0xffffffffu, s, o);
        float val = __fadd_rn(s, bcls[c]);    // cas value incl. bias
        if (lane == c) mine = val;
        dtot += (double)val;                  // exact class-sum
    }

    if (lane < CDIM) casOut[row * CDIM + lane] = mine;
    if (lane == 0)   g_a[row] = (float)dtot;
}

// ---------------- K3: circular smoothing (double internal) ----------------
__global__ void smooth_kernel(float* __restrict__ actOut) {
    const int b = blockIdx.x, t = threadIdx.x;
    __shared__ float a[TDIM];
    if (t < TDIM) a[t] = g_a[b * TDIM + t];
    __syncthreads();
    if (t < TDIM) {
        int p1 = (t + 1) % TDIM,  m1 = (t + TDIM - 1) % TDIM;
        int p2 = (t + 2) % TDIM,  m2 = (t + TDIM - 2) % TDIM;
        double v = (double)a[t]
                 + 0.1  * (double)a[p1] + 0.1  * (double)a[m1]
                 + 0.02 * (double)a[p2] + 0.02 * (double)a[m2];
        float vf = (float)v;
        g_act[b * TDIM + t]  = vf;
        actOut[b * TDIM + t] = vf;
    }
}

// ---------------- bitonic sorts (blockDim = 1024) ----------------
__device__ void bitonic_f(float* d, int tid, bool desc) {
    for (int k = 2; k <= 1024; k <<= 1)
        for (int j = k >> 1; j > 0; j >>= 1) {
            int x = tid ^ j;
            if (x > tid) {
                float a = d[tid], b = d[x];
                bool up = ((tid & k) == 0) != desc;
                if (up ? (a > b) : (a < b)) { d[tid] = b; d[x] = a; }
            }
            __syncthreads();
        }
}
__device__ void bitonic_u64_desc(ull* d, int tid) {
    for (int k = 2; k <= 1024; k <<= 1)
        for (int j = k >> 1; j > 0; j >>= 1) {
            int x = tid ^ j;
            if (x > tid) {
                ull a = d[tid], b = d[x];
                bool up = ((tid & k) == 0);
                if (up ? (a < b) : (a > b)) { d[tid] = b; d[x] = a; }
            }
            __syncthreads();
        }
}

// ---------------- K4: per-batch median/max/morphology + 4 index top-ks ----
__global__ void __launch_bounds__(1024) stats_topk_kernel() {
    const int b = blockIdx.x, tid = threadIdx.x;
    __shared__ float act[TDIM];
    __shared__ float abin[TDIM];
    __shared__ float sv[1024];
    __shared__ ull   keys[1024];
    __shared__ float scal[2];

    const float NI = __int_as_float(0xff800000);
    const float PI = __int_as_float(0x7f800000);

    if (tid < TDIM) act[tid] = g_act[b * TDIM + tid];
    __syncthreads();

    sv[tid] = (tid < TDIM) ? act[tid] : NI;
    __syncthreads();
    for (int s = 512; s > 0; s >>= 1) {
        if (tid < s) sv[tid] = fmaxf(sv[tid], sv[tid + s]);
        __syncthreads();
    }
    if (tid == 0) scal[0] = sv[0];
    __syncthreads();

    sv[tid] = (tid < TDIM) ? act[tid] : PI;
    __syncthreads();
    bitonic_f(sv, tid, false);
    if (tid == 0)
        scal[1] = __fmul_rn(0.5f, __fadd_rn(sv[374], sv[375]));
    __syncthreads();

    const float amax = scal[0], med = scal[1];
    if (tid < TDIM) abin[tid] = (act[tid] > med) ? 1.f : 0.f;
    __syncthreads();

    float sc[4] = {0.f, 0.f, 0.f, 0.f};
    if (tid < TDIM) {
        const int t = tid;
        const float a = act[t];
        float e3 = (t >= 1 && t <= TDIM - 2)
                       ? fminf(fminf(abin[t - 1], abin[t]), abin[t + 1]) : 0.f;
        float e6 = 0.f;
        if (t >= 3 && t <= TDIM - 3) {
            e6 = fminf(fminf(fminf(abin[t - 3], abin[t - 2]), fminf(abin[t - 1], abin[t])),
                       fminf(abin[t + 1], abin[t + 2]));
        }
        float d3 = abin[t];
        if (t >= 1)        d3 = fmaxf(d3, abin[t - 1]);
        if (t <= TDIM - 2) d3 = fmaxf(d3, abin[t + 1]);
        float d6 = abin[t];
        if (t >= 1)        d6 = fmaxf(d6, abin[t - 1]);
        if (t >= 2)        d6 = fmaxf(d6, abin[t - 2]);
        if (t <= TDIM - 2) d6 = fmaxf(d6, abin[t + 1]);
        if (t <= TDIM - 3) d6 = fmaxf(d6, abin[t + 2]);
        if (t <= TDIM - 4) d6 = fmaxf(d6, abin[t + 3]);

        sc[0] = a;
        sc[1] = __fsub_rn(amax, a);
        sc[2] = __fmul_rn(a, __fsub_rn(e3, e6));
        sc[3] = __fmul_rn(a, __fsub_rn(d6, d3));
    }

    const int kk[4]  = {KEASY, KEASY, KHARD, KHARD};
    const int off[4] = {IDX_EA, IDX_EB, IDX_HA, IDX_HB};
    for (int pass = 0; pass < 4; ++pass) {
        __syncthreads();
        ull key = 0ull;
        if (tid < TDIM) {
            unsigned u = __float_as_uint(sc[pass]);
            u = (u & 0x80000000u) ? ~u : (u | 0x80000000u);
            key = ((ull)u << 32) | (ull)(0xFFFFFFFFu - (unsigned)tid);
        }
        keys[tid] = key;
        __syncthreads();
        bitonic_u64_desc(keys, tid);
        if (tid < kk[pass]) {
            unsigned idx = 0xFFFFFFFFu - (unsigned)(keys[tid] & 0xFFFFFFFFull);
            g_idx[off[pass] + b * kk[pass] + tid] = (int)idx;
        }
    }
}

// ---------------- K5: per-(b,c) top-150 mean of cas over time ----------------
__global__ void __launch_bounds__(1024) classtopk_kernel(const float* __restrict__ cas) {
    const int bc = blockIdx.x;
    const int b = bc / CDIM, c = bc % CDIM;
    const int tid = threadIdx.x;
    __shared__ float sv[1024];
    sv[tid] = (tid < TDIM) ? cas[(b * TDIM + tid) * CDIM + c] : __int_as_float(0xff800000);
    __syncthreads();
    bitonic_f(sv, tid, true);
    if (tid == 0) {
        float s = 0.f;
        for (int i = 0; i < KEASY; ++i) s = __fadd_rn(s, sv[i]);
        g_vmean[bc] = s / (float)KEASY;
    }
}

// ---------------- K6: softmax over classes ----------------
__global__ void softmax_kernel(float* __restrict__ vs) {
    const int lane = threadIdx.x & 31, w = threadIdx.x >> 5;
    if (w >= BDIM) return;
    float v = (lane < CDIM) ? g_vmean[w * CDIM + lane] : __int_as_float(0xff800000);
    float m = v;
    #pragma unroll
    for (int o = 16; o; o >>= 1) m = fmaxf(m, __shfl_xor_sync(0xffffffffu, m, o));
    float e = (lane < CDIM) ? expf(v - m) : 0.f;
    float s = e;
    #pragma unroll
    for (int o = 16; o; o >>= 1) s += __shfl_xor_sync(0xffffffffu, s, o);
    if (lane < CDIM) vs[w * CDIM + lane] = e / s;
}

// ---------------- K7: gather selected embedding rows ----------------
__global__ void __launch_bounds__(256) gather_kernel(const int* __restrict__ idx,
                                                     int k, float* __restrict__ dst) {
    const int r = blockIdx.x;
    const int b = r / k;
    const int t = idx[r];
    const float4* src = reinterpret_cast<const float4*>(
        g_emb + (size_t)(b * TDIM + t) * EMBD);
    float4* out = reinterpret_cast<float4*>(dst + (size_t)r * EMBD);
    #pragma unroll
    for (int i = 0; i < 2; ++i)
        out[threadIdx.x + 256 * i] = src[threadIdx.x + 256 * i];
}

// ---------------- launcher ----------------
extern "C" void kernel_launch(void* const* d_in, const int* in_sizes, int n_in,
                              void* d_out, int out_size) {
    (void)in_sizes; (void)n_in; (void)out_size;
    const float* x       = (const float*)d_in[0];
    const float* W_embed = (const float*)d_in[1];
    const float* b_embed = (const float*)d_in[2];
    const float* W_cls   = (const float*)d_in[3];
    const float* b_cls   = (const float*)d_in[4];
    float* out = (float*)d_out;

    int* idxp;
    cudaGetSymbolAddress((void**)&idxp, g_idx);

    transposeW_kernel<<<dim3(KTOT / 32, EMBD / 32), 256>>>(W_embed);
    gemm1_kernel<<<dim3(EMBD / 128, (MTOT + 127) / 128, KSPLIT), 256>>>(x);
    {
        size_t n4 = (size_t)MTOT * EMBD / 4;
        combine_kernel<<<(unsigned)((n4 + 255) / 256), 256>>>(b_embed);
    }
    cas_kernel<<<MTOT / 8, 256>>>(W_cls, b_cls, out + OFF_CAS);
    smooth_kernel<<<BDIM, 768>>>(out + OFF_ACT);
    stats_topk_kernel<<<BDIM, 1024>>>();
    classtopk_kernel<<<BDIM * CDIM, 1024>>>(out + OFF_CAS);
    softmax_kernel<<<1, 1024>>>(out + OFF_VS);
    gather_kernel<<<BDIM * KEASY, 256>>>(idxp + IDX_EA, KEASY, out + OFF_EA);
    gather_kernel<<<BDIM * KEASY, 256>>>(idxp + IDX_EB, KEASY, out + OFF_EB);
    gather_kernel<<<BDIM * KHARD, 256>>>(idxp + IDX_HA, KHARD, out + OFF_HA);
    gather_kernel<<<BDIM * KHARD, 256>>>(idxp + IDX_HB, KHARD, out + OFF_HB);
}

// round 14
// speedup vs baseline: 1.2498x; 1.2486x over previous
#include <cuda_runtime.h>
#include <cuda_bf16.h>
#include <cuda_fp16.h>
#include <cstdint>
#include <math.h>

#define BDIM   32
#define TDIM   750
#define TPAD   768
#define TROWS  770
#define FDIM   2048
#define EMBD   2048
#define CDIM   20
#define KTOT   6144
#define MTOT   (BDIM * TDIM)
#define MPAD   (BDIM * TPAD)
#define KEASY  150
#define KHARD  37

#define ZSPLIT 8
#define KC     64
#define CPZ    (KTOT / ZSPLIT / KC)   // 12
#define NPROD  4
#define NCHUNK (NPROD * CPZ)          // 48
#define NSTAGE 3
#define STAGE_BYTES 32768             // A 16KB + B 16KB
#define SM_TOTAL (NSTAGE * STAGE_BYTES)

#define OFF_VS   0
#define SZ_VS    (BDIM * CDIM)
#define OFF_EA   (OFF_VS + SZ_VS)
#define SZ_EA    (BDIM * KEASY * EMBD)
#define OFF_EB   (OFF_EA + SZ_EA)
#define OFF_HA   (OFF_EB + SZ_EA)
#define SZ_HA    (BDIM * KHARD * EMBD)
#define OFF_HB   (OFF_HA + SZ_HA)
#define OFF_ACT  (OFF_HB + SZ_HA)
#define OFF_CAS  (OFF_ACT + BDIM * TDIM)

#define IDX_EA 0
#define IDX_EB (BDIM * KEASY)
#define IDX_HA (2 * BDIM * KEASY)
#define IDX_HB (IDX_HA + BDIM * KHARD)

typedef unsigned long long ull;

#define XROWS (BDIM * TROWS)
#define XT    ((size_t)XROWS * FDIM)
#define WT    ((size_t)EMBD * KTOT)

__device__ __half g_xs2[2 * XT];          // [0]=hi, [1]=lo
__device__ __half g_ws2[2 * WT];          // [0]=hi, [1]=lo (W pre-scaled x1024)
__device__ float g_part[(size_t)ZSPLIT * MTOT * EMBD];
__device__ float g_emb[(size_t)MTOT * EMBD];
__device__ float g_a[MTOT];
__device__ float g_act[MTOT];
__device__ int   g_idx[IDX_HB + BDIM * KHARD];
__device__ float g_vmean[BDIM * CDIM];

// products ascending magnitude: (lo,lo), (hi,lo), (lo,hi), (hi,hi)
__constant__ int c_PA[NPROD] = {1, 0, 1, 0};
__constant__ int c_PB[NPROD] = {1, 1, 0, 0};

// ---------------- PTX helpers ----------------
__device__ __forceinline__ uint32_t smem_u32(const void* p) {
    uint32_t a;
    asm("{ .reg .u64 t; cvta.to.shared.u64 t, %1; cvt.u32.u64 %0, t; }" : "=r"(a) : "l"(p));
    return a;
}
__device__ __forceinline__ void cp16(uint32_t dst, const void* src) {
    asm volatile("cp.async.cg.shared.global [%0], [%1], 16;" :: "r"(dst), "l"(src));
}
#define CP_COMMIT() asm volatile("cp.async.commit_group;" ::: "memory")
#define CP_WAIT2()  asm volatile("cp.async.wait_group 2;" ::: "memory")

__device__ __forceinline__ void ldsm4(uint32_t* r, uint32_t addr) {
    asm volatile("ldmatrix.sync.aligned.m8n8.x4.shared.b16 {%0,%1,%2,%3}, [%4];"
                 : "=r"(r[0]), "=r"(r[1]), "=r"(r[2]), "=r"(r[3]) : "r"(addr));
}
__device__ __forceinline__ void mma16816(float* c, const uint32_t* a, const uint32_t* b) {
    asm volatile("mma.sync.aligned.m16n8k16.row.col.f32.f16.f16.f32 "
                 "{%0,%1,%2,%3}, {%4,%5,%6,%7}, {%8,%9}, {%0,%1,%2,%3};"
                 : "+f"(c[0]), "+f"(c[1]), "+f"(c[2]), "+f"(c[3])
                 : "r"(a[0]), "r"(a[1]), "r"(a[2]), "r"(a[3]), "r"(b[0]), "r"(b[1]));
}
__device__ __forceinline__ uint32_t swz(uint32_t off) { return off ^ ((off >> 3) & 0x70); }

// ---------------- K0a: split x -> 2 fp16 comps, padded rows (t=-1..768) ----
__global__ void __launch_bounds__(256) splitx_kernel(const float* __restrict__ x) {
    size_t i = (size_t)blockIdx.x * 256 + threadIdx.x;
    if (i >= XT) return;
    int row = (int)(i >> 11), f = (int)(i & 2047);
    int b = row / TROWS, t = row % TROWS - 1;
    float v = (t >= 0 && t < TDIM) ? x[((size_t)b * TDIM + t) * FDIM + f] : 0.f;
    __half hi = __float2half_rn(v);
    g_xs2[i] = hi;
    g_xs2[XT + i] = __float2half_rn(v - __half2float(hi));
}

// ---------------- K0b: split W*1024 -> 2 fp16, layout [e][k], k=tap*2048+f --
__global__ void __launch_bounds__(256) splitw_kernel(const float* __restrict__ W) {
    size_t i = (size_t)blockIdx.x * 256 + threadIdx.x;
    if (i >= WT) return;
    int e = (int)(i / KTOT), k = (int)(i % KTOT);
    int tap = k >> 11, f = k & 2047;
    float v = W[(size_t)e * KTOT + f * 3 + tap] * 1024.f;
    __half hi = __float2half_rn(v);
    g_ws2[i] = hi;
    g_ws2[WT + i] = __float2half_rn(v - __half2float(hi));
}

// ---------------- K1: HMMA fp16-split GEMM 128x128 tile, split-K z=8 -------
__global__ void __launch_bounds__(256) gemm_hmma_kernel() {
    extern __shared__ __align__(128) char smem[];
    const uint32_t sb = smem_u32(smem);
    const int tid = threadIdx.x, wid = tid >> 5, lane = tid & 31;
    const int n0 = blockIdx.x * 128;
    const int m0 = blockIdx.y * 128;
    const int z  = blockIdx.z;
    const int bb = m0 / TPAD, t0 = m0 % TPAD;
    const long rowbase = (long)bb * TROWS + t0;
    const int wm = wid & 3, wn = wid >> 2;

    float c[2][8][4];    // grand accumulator
    float cc[2][8][4];   // fresh per-chunk accumulator for hh product
    #pragma unroll
    for (int i = 0; i < 2; ++i)
        #pragma unroll
        for (int j = 0; j < 8; ++j)
            #pragma unroll
            for (int v = 0; v < 4; ++v) c[i][j][v] = 0.f;

    const int frow = tid >> 1, fh = (tid & 1) * 64;   // fill row + byte-half

    auto fill = [&](int q, int s) {
        const int p = q / CPZ;
        const int k0 = z * (KTOT / ZSPLIT) + (q % CPZ) * KC;
        const int tap = k0 >> 11, f0 = k0 & 2047;
        const uint32_t base = sb + s * STAGE_BYTES;
        const char* ga = (const char*)(g_xs2 + (size_t)c_PA[p] * XT
                         + (size_t)(rowbase + tap + frow) * FDIM + f0) + fh;
        const char* gb = (const char*)(g_ws2 + (size_t)c_PB[p] * WT
                         + (size_t)(n0 + frow) * KTOT + k0) + fh;
        #pragma unroll
        for (int i = 0; i < 4; ++i) {
            uint32_t off = swz((uint32_t)(frow * 128 + fh + i * 16));
            cp16(base + off, ga + i * 16);
            cp16(base + 16384 + off, gb + i * 16);
        }
    };

    // whole-chunk mma into accumulator C
    auto domma = [&](float (&C)[2][8][4], uint32_t sA, uint32_t sB) {
        #pragma unroll
        for (int kk = 0; kk < 4; ++kk) {
            uint32_t a[2][4];
            #pragma unroll
            for (int i = 0; i < 2; ++i) {
                int r = wm * 32 + i * 16 + (lane & 15);
                int cg = kk * 2 + (lane >> 4);
                ldsm4(a[i], sA + swz((uint32_t)(r * 128 + cg * 16)));
            }
            uint32_t b[8][2];
            #pragma unroll
            for (int j = 0; j < 4; ++j) {
                int r = wn * 64 + j * 16 + (lane >> 4) * 8 + (lane & 7);
                int cg = kk * 2 + ((lane >> 3) & 1);
                uint32_t qr[4];
                ldsm4(qr, sB + swz((uint32_t)(r * 128 + cg * 16)));
                b[2 * j][0] = qr[0]; b[2 * j][1] = qr[1];
                b[2 * j + 1][0] = qr[2]; b[2 * j + 1][1] = qr[3];
            }
            #pragma unroll
            for (int i = 0; i < 2; ++i)
                #pragma unroll
                for (int j = 0; j < 8; ++j) mma16816(C[i][j], a[i], b[j]);
        }
    };

    fill(0, 0); CP_COMMIT();
    fill(1, 1); CP_COMMIT();

    for (int q = 0; q < NCHUNK; ++q) {
        if (q + 2 < NCHUNK) fill(q + 2, (q + 2) % NSTAGE);
        CP_COMMIT();
        CP_WAIT2();
        __syncthreads();

        const uint32_t sA = sb + (q % NSTAGE) * STAGE_BYTES;
        const uint32_t sB = sA + 16384;
        const bool fresh = (q / CPZ == NPROD - 1);   // hh product: blocked accumulation
        if (fresh) {
            #pragma unroll
            for (int i = 0; i < 2; ++i)
                #pragma unroll
                for (int j = 0; j < 8; ++j)
                    #pragma unroll
                    for (int v = 0; v < 4; ++v) cc[i][j][v] = 0.f;
            domma(cc, sA, sB);
            #pragma unroll
            for (int i = 0; i < 2; ++i)
                #pragma unroll
                for (int j = 0; j < 8; ++j)
                    #pragma unroll
                    for (int v = 0; v < 4; ++v) c[i][j][v] = __fadd_rn(c[i][j][v], cc[i][j][v]);
        } else {
            domma(c, sA, sB);
        }
        __syncthreads();
    }

    // epilogue -> g_part[z]
    const int grp = lane >> 2, qd = lane & 3;
    float* zbase = g_part + (size_t)z * MTOT * EMBD;
    #pragma unroll
    for (int i = 0; i < 2; ++i) {
        #pragma unroll
        for (int h = 0; h < 2; ++h) {
            int t = t0 + wm * 32 + i * 16 + grp + h * 8;
            if (t < TDIM) {
                float* dst = zbase + ((size_t)bb * TDIM + t) * EMBD + n0 + wn * 64 + qd * 2;
                #pragma unroll
                for (int j = 0; j < 8; ++j) {
                    float2 v2 = make_float2(c[i][j][h * 2], c[i][j][h * 2 + 1]);
                    *reinterpret_cast<float2*>(dst + j * 8) = v2;
                }
            }
        }
    }
}

// ---------------- K1b: combine 8 partials in double (exact) + bias + relu --
__global__ void __launch_bounds__(256) combine_kernel(const float* __restrict__ bE) {
    const size_t N4 = (size_t)MTOT * EMBD / 4;
    size_t i = (size_t)blockIdx.x * 256 + threadIdx.x;
    if (i >= N4) return;
    const float4* P = reinterpret_cast<const float4*>(g_part);
    float4 s[8];
    #pragma unroll
    for (int j = 0; j < 8; ++j) s[j] = P[i + j * N4];
    int e = (int)((i * 4) & (EMBD - 1));
    float4 b = *reinterpret_cast<const float4*>(bE + e);
    const double SC = 1.0 / 1024.0;
    float4 o;
    #define CMB(f) { double t_ = 0.0; \
        t_ += (double)s[0].f; t_ += (double)s[1].f; t_ += (double)s[2].f; t_ += (double)s[3].f; \
        t_ += (double)s[4].f; t_ += (double)s[5].f; t_ += (double)s[6].f; t_ += (double)s[7].f; \
        o.f = fmaxf((float)(t_ * SC + (double)b.f), 0.f); }
    CMB(x); CMB(y); CMB(z); CMB(w);
    #undef CMB
    reinterpret_cast<float4*>(g_emb)[i] = o;
}

// ---------------- K2: classifier + actionness ----------------
__global__ void __launch_bounds__(256) cas_kernel(const float* __restrict__ Wcls,
                                                  const float* __restrict__ bcls,
                                                  float* __restrict__ casOut) {
    __shared__ float Ws[512][21];
    const int tid = threadIdx.x, lane = tid & 31, warp = tid >> 5;
    const int row = blockIdx.x * 8 + warp;
    float acc[CDIM];
    #pragma unroll
    for (int c = 0; c < CDIM; ++c) acc[c] = 0.f;
    for (int ch = 0; ch < 4; ++ch) {
        __syncthreads();
        for (int idx = tid; idx < 512 * CDIM; idx += 256) {
            int c = idx >> 9, e = idx & 511;
            Ws[e][c] = Wcls[c * EMBD + ch * 512 + e];
        }
        __syncthreads();
        const float* er = g_emb + (size_t)row * EMBD + ch * 512;
        #pragma unroll 4
        for (int eb = 0; eb < 512; eb += 32) {
            float v = er[eb + lane];
            const float* wr = &Ws[eb + lane][0];
            #pragma unroll
            for (int c = 0; c < CDIM; ++c) acc[c] = fmaf(v, wr[c], acc[c]);
        }
    }
    double dtot = 0.0;
    float mine = 0.f;
    #pragma unroll
    for (int c = 0; c < CDIM; ++c) {
        float s = acc[c];
        #pragma unroll
        for (int o = 16; o; o >>= 1) s += __shfl_xor_sync(0xffffffffu, s, o);
        float val = __fadd_rn(s, bcls[c]);
        if (lane == c) mine = val;
        dtot += (double)val;
    }
    if (lane < CDIM) casOut[row * CDIM + lane] = mine;
    if (lane == 0)   g_a[row] = (float)dtot;
}

// ---------------- K3: circular smoothing ----------------
__global__ void smooth_kernel(float* __restrict__ actOut) {
    const int b = blockIdx.x, t = threadIdx.x;
    __shared__ float a[TDIM];
    if (t < TDIM) a[t] = g_a[b * TDIM + t];
    __syncthreads();
    if (t < TDIM) {
        int p1 = (t + 1) % TDIM,  m1 = (t + TDIM - 1) % TDIM;
        int p2 = (t + 2) % TDIM,  m2 = (t + TDIM - 2) % TDIM;
        double v = (double)a[t]
                 + 0.1  * (double)a[p1] + 0.1  * (double)a[m1]
                 + 0.02 * (double)a[p2] + 0.02 * (double)a[m2];
        float vf = (float)v;
        g_act[b * TDIM + t]  = vf;
        actOut[b * TDIM + t] = vf;
    }
}

// ---------------- bitonic sorts (blockDim = 1024) ----------------
__device__ void bitonic_f(float* d, int tid, bool desc) {
    for (int k = 2; k <= 1024; k <<= 1)
        for (int j = k >> 1; j > 0; j >>= 1) {
            int x = tid ^ j;
            if (x > tid) {
                float a = d[tid], b = d[x];
                bool up = ((tid & k) == 0) != desc;
                if (up ? (a > b) : (a < b)) { d[tid] = b; d[x] = a; }
            }
            __syncthreads();
        }
}
__device__ void bitonic_u64_desc(ull* d, int tid) {
    for (int k = 2; k <= 1024; k <<= 1)
        for (int j = k >> 1; j > 0; j >>= 1) {
            int x = tid ^ j;
            if (x > tid) {
                ull a = d[tid], b = d[x];
                bool up = ((tid & k) == 0);
                if (up ? (a < b) : (a > b)) { d[tid] = b; d[x] = a; }
            }
            __syncthreads();
        }
}

// ---------------- K4: per-batch stats + 4 index top-ks ----------------
__global__ void __launch_bounds__(1024) stats_topk_kernel() {
    const int b = blockIdx.x, tid = threadIdx.x;
    __shared__ float act[TDIM];
    __shared__ float abin[TDIM];
    __shared__ float sv[1024];
    __shared__ ull   keys[1024];
    __shared__ float scal[2];
    const float NI = __int_as_float(0xff800000);
    const float PI = __int_as_float(0x7f800000);

    if (tid < TDIM) act[tid] = g_act[b * TDIM + tid];
    __syncthreads();
    sv[tid] = (tid < TDIM) ? act[tid] : NI;
    __syncthreads();
    for (int s = 512; s > 0; s >>= 1) {
        if (tid < s) sv[tid] = fmaxf(sv[tid], sv[tid + s]);
        __syncthreads();
    }
    if (tid == 0) scal[0] = sv[0];
    __syncthreads();
    sv[tid] = (tid < TDIM) ? act[tid] : PI;
    __syncthreads();
    bitonic_f(sv, tid, false);
    if (tid == 0) scal[1] = __fmul_rn(0.5f, __fadd_rn(sv[374], sv[375]));
    __syncthreads();

    const float amax = scal[0], med = scal[1];
    if (tid < TDIM) abin[tid] = (act[tid] > med) ? 1.f : 0.f;
    __syncthreads();

    float sc[4] = {0.f, 0.f, 0.f, 0.f};
    if (tid < TDIM) {
        const int t = tid;
        const float a = act[t];
        float e3 = (t >= 1 && t <= TDIM - 2)
                       ? fminf(fminf(abin[t - 1], abin[t]), abin[t + 1]) : 0.f;
        float e6 = 0.f;
        if (t >= 3 && t <= TDIM - 3)
            e6 = fminf(fminf(fminf(abin[t - 3], abin[t - 2]), fminf(abin[t - 1], abin[t])),
                       fminf(abin[t + 1], abin[t + 2]));
        float d3 = abin[t];
        if (t >= 1)        d3 = fmaxf(d3, abin[t - 1]);
        if (t <= TDIM - 2) d3 = fmaxf(d3, abin[t + 1]);
        float d6 = abin[t];
        if (t >= 1)        d6 = fmaxf(d6, abin[t - 1]);
        if (t >= 2)        d6 = fmaxf(d6, abin[t - 2]);
        if (t <= TDIM - 2) d6 = fmaxf(d6, abin[t + 1]);
        if (t <= TDIM - 3) d6 = fmaxf(d6, abin[t + 2]);
        if (t <= TDIM - 4) d6 = fmaxf(d6, abin[t + 3]);
        sc[0] = a;
        sc[1] = __fsub_rn(amax, a);
        sc[2] = __fmul_rn(a, __fsub_rn(e3, e6));
        sc[3] = __fmul_rn(a, __fsub_rn(d6, d3));
    }

    const int kk[4]  = {KEASY, KEASY, KHARD, KHARD};
    const int off[4] = {IDX_EA, IDX_EB, IDX_HA, IDX_HB};
    for (int pass = 0; pass < 4; ++pass) {
        __syncthreads();
        ull key = 0ull;
        if (tid < TDIM) {
            unsigned u = __float_as_uint(sc[pass]);
            u = (u & 0x80000000u) ? ~u : (u | 0x80000000u);
            key = ((ull)u << 32) | (ull)(0xFFFFFFFFu - (unsigned)tid);
        }
        keys[tid] = key;
        __syncthreads();
        bitonic_u64_desc(keys, tid);
        if (tid < kk[pass]) {
            unsigned idx = 0xFFFFFFFFu - (unsigned)(keys[tid] & 0xFFFFFFFFull);
            g_idx[off[pass] + b * kk[pass] + tid] = (int)idx;
        }
    }
}

// ---------------- K5: per-(b,c) top-150 mean of cas ----------------
__global__ void __launch_bounds__(1024) classtopk_kernel(const float* __restrict__ cas) {
    const int bc = blockIdx.x;
    const int b = bc / CDIM, c = bc % CDIM;
    const int tid = threadIdx.x;
    __shared__ float sv[1024];
    sv[tid] = (tid < TDIM) ? cas[(b * TDIM + tid) * CDIM + c] : __int_as_float(0xff800000);
    __syncthreads();
    bitonic_f(sv, tid, true);
    if (tid == 0) {
        float s = 0.f;
        for (int i = 0; i < KEASY; ++i) s = __fadd_rn(s, sv[i]);
        g_vmean[bc] = s / (float)KEASY;
    }
}

// ---------------- K6: softmax ----------------
__global__ void softmax_kernel(float* __restrict__ vs) {
    const int lane = threadIdx.x & 31, w = threadIdx.x >> 5;
    if (w >= BDIM) return;
    float v = (lane < CDIM) ? g_vmean[w * CDIM + lane] : __int_as_float(0xff800000);
    float m = v;
    #pragma unroll
    for (int o = 16; o; o >>= 1) m = fmaxf(m, __shfl_xor_sync(0xffffffffu, m, o));
    float e = (lane < CDIM) ? expf(v - m) : 0.f;
    float s = e;
    #pragma unroll
    for (int o = 16; o; o >>= 1) s += __shfl_xor_sync(0xffffffffu, s, o);
    if (lane < CDIM) vs[w * CDIM + lane] = e / s;
}

// ---------------- K7: gather ----------------
__global__ void __launch_bounds__(256) gather_kernel(const int* __restrict__ idx,
                                                     int k, float* __restrict__ dst) {
    const int r = blockIdx.x;
    const int b = r / k;
    const int t = idx[r];
    const float4* src = reinterpret_cast<const float4*>(
        g_emb + (size_t)(b * TDIM + t) * EMBD);
    float4* out = reinterpret_cast<float4*>(dst + (size_t)r * EMBD);
    #pragma unroll
    for (int i = 0; i < 2; ++i)
        out[threadIdx.x + 256 * i] = src[threadIdx.x + 256 * i];
}

// ---------------- launcher ----------------
extern "C" void kernel_launch(void* const* d_in, const int* in_sizes, int n_in,
                              void* d_out, int out_size) {
    (void)in_sizes; (void)n_in; (void)out_size;
    const float* x       = (const float*)d_in[0];
    const float* W_embed = (const float*)d_in[1];
    const float* b_embed = (const float*)d_in[2];
    const float* W_cls   = (const float*)d_in[3];
    const float* b_cls   = (const float*)d_in[4];
    float* out = (float*)d_out;

    int* idxp;
    cudaGetSymbolAddress((void**)&idxp, g_idx);
    cudaFuncSetAttribute(gemm_hmma_kernel,
                         cudaFuncAttributeMaxDynamicSharedMemorySize, SM_TOTAL);

    splitx_kernel<<<(unsigned)((XT + 255) / 256), 256>>>(x);
    splitw_kernel<<<(unsigned)((WT + 255) / 256), 256>>>(W_embed);
    gemm_hmma_kernel<<<dim3(EMBD / 128, MPAD / 128, ZSPLIT), 256, SM_TOTAL>>>();
    {
        size_t n4 = (size_t)MTOT * EMBD / 4;
        combine_kernel<<<(unsigned)((n4 + 255) / 256), 256>>>(b_embed);
    }
    cas_kernel<<<MTOT / 8, 256>>>(W_cls, b_cls, out + OFF_CAS);
    smooth_kernel<<<BDIM, 768>>>(out + OFF_ACT);
    stats_topk_kernel<<<BDIM, 1024>>>();
    classtopk_kernel<<<BDIM * CDIM, 1024>>>(out + OFF_CAS);
    softmax_kernel<<<1, 1024>>>(out + OFF_VS);
    gather_kernel<<<BDIM * KEASY, 256>>>(idxp + IDX_EA, KEASY, out + OFF_EA);
    gather_kernel<<<BDIM * KEASY, 256>>>(idxp + IDX_EB, KEASY, out + OFF_EB);
    gather_kernel<<<BDIM * KHARD, 256>>>(idxp + IDX_HA, KHARD, out + OFF_HA);
    gather_kernel<<<BDIM * KHARD, 256>>>(idxp + IDX_HB, KHARD, out + OFF_HB);
}

// round 16
// speedup vs baseline: 1.3984x; 1.1189x over previous
#include <cuda_runtime.h>
#include <cuda_bf16.h>
#include <cuda_fp16.h>
#include <cstdint>
#include <math.h>

#define BDIM   32
#define TDIM   750
#define TPAD   768
#define TROWS  770
#define FDIM   2048
#define EMBD   2048
#define CDIM   20
#define KTOT   6144
#define MTOT   (BDIM * TDIM)
#define MPAD   (BDIM * TPAD)
#define KEASY  150
#define KHARD  37

#define ZSPLIT 8
#define KC     64
#define CPZ    (KTOT / ZSPLIT / KC)   // 12
#define NPROD  4
#define NCHUNK (NPROD * CPZ)          // 48
#define NSTAGE 4
#define STAGE_BYTES 32768             // A 16KB + B 16KB
#define SM_TOTAL (NSTAGE * STAGE_BYTES)   // 128KB

#define OFF_VS   0
#define SZ_VS    (BDIM * CDIM)
#define OFF_EA   (OFF_VS + SZ_VS)
#define SZ_EA    (BDIM * KEASY * EMBD)
#define OFF_EB   (OFF_EA + SZ_EA)
#define OFF_HA   (OFF_EB + SZ_EA)
#define SZ_HA    (BDIM * KHARD * EMBD)
#define OFF_HB   (OFF_HA + SZ_HA)
#define OFF_ACT  (OFF_HB + SZ_HA)
#define OFF_CAS  (OFF_ACT + BDIM * TDIM)

#define IDX_EA 0
#define IDX_EB (BDIM * KEASY)
#define IDX_HA (2 * BDIM * KEASY)
#define IDX_HB (IDX_HA + BDIM * KHARD)

typedef unsigned long long ull;

#define XROWS (BDIM * TROWS)
#define XT    ((size_t)XROWS * FDIM)
#define WT    ((size_t)EMBD * KTOT)

__device__ __half g_xs2[2 * XT];          // [0]=hi, [1]=lo
__device__ __half g_ws2[2 * WT];          // [0]=hi, [1]=lo (W pre-scaled x1024)
__device__ float g_part[(size_t)ZSPLIT * MTOT * EMBD];
__device__ float g_emb[(size_t)MTOT * EMBD];
__device__ float g_a[MTOT];
__device__ float g_act[MTOT];
__device__ int   g_idx[IDX_HB + BDIM * KHARD];
__device__ float g_vmean[BDIM * CDIM];

// products ascending magnitude: (lo,lo), (hi,lo), (lo,hi), (hi,hi)
__constant__ int c_PA[NPROD] = {1, 0, 1, 0};
__constant__ int c_PB[NPROD] = {1, 1, 0, 0};

// ---------------- PTX helpers ----------------
__device__ __forceinline__ uint32_t smem_u32(const void* p) {
    uint32_t a;
    asm("{ .reg .u64 t; cvta.to.shared.u64 t, %1; cvt.u32.u64 %0, t; }" : "=r"(a) : "l"(p));
    return a;
}
__device__ __forceinline__ void cp16(uint32_t dst, const void* src) {
    asm volatile("cp.async.cg.shared.global [%0], [%1], 16;" :: "r"(dst), "l"(src));
}
#define CP_COMMIT() asm volatile("cp.async.commit_group;" ::: "memory")
#define CP_WAIT2()  asm volatile("cp.async.wait_group 2;" ::: "memory")

__device__ __forceinline__ void ldsm4(uint32_t* r, uint32_t addr) {
    asm volatile("ldmatrix.sync.aligned.m8n8.x4.shared.b16 {%0,%1,%2,%3}, [%4];"
                 : "=r"(r[0]), "=r"(r[1]), "=r"(r[2]), "=r"(r[3]) : "r"(addr));
}
__device__ __forceinline__ void mma16816(float* c, const uint32_t* a, const uint32_t* b) {
    asm volatile("mma.sync.aligned.m16n8k16.row.col.f32.f16.f16.f32 "
                 "{%0,%1,%2,%3}, {%4,%5,%6,%7}, {%8,%9}, {%0,%1,%2,%3};"
                 : "+f"(c[0]), "+f"(c[1]), "+f"(c[2]), "+f"(c[3])
                 : "r"(a[0]), "r"(a[1]), "r"(a[2]), "r"(a[3]), "r"(b[0]), "r"(b[1]));
}
__device__ __forceinline__ uint32_t swz(uint32_t off) { return off ^ ((off >> 3) & 0x70); }

// ---------------- K0a: split x -> 2 fp16 comps, padded rows (t=-1..768) ----
__global__ void __launch_bounds__(256) splitx_kernel(const float* __restrict__ x) {
    size_t i = (size_t)blockIdx.x * 256 + threadIdx.x;
    if (i >= XT) return;
    int row = (int)(i >> 11), f = (int)(i & 2047);
    int b = row / TROWS, t = row % TROWS - 1;
    float v = (t >= 0 && t < TDIM) ? x[((size_t)b * TDIM + t) * FDIM + f] : 0.f;
    __half hi = __float2half_rn(v);
    g_xs2[i] = hi;
    g_xs2[XT + i] = __float2half_rn(v - __half2float(hi));
}

// ---------------- K0b: split W*1024 -> 2 fp16, layout [e][k], k=tap*2048+f --
__global__ void __launch_bounds__(256) splitw_kernel(const float* __restrict__ W) {
    size_t i = (size_t)blockIdx.x * 256 + threadIdx.x;
    if (i >= WT) return;
    int e = (int)(i / KTOT), k = (int)(i % KTOT);
    int tap = k >> 11, f = k & 2047;
    float v = W[(size_t)e * KTOT + f * 3 + tap] * 1024.f;
    __half hi = __float2half_rn(v);
    g_ws2[i] = hi;
    g_ws2[WT + i] = __float2half_rn(v - __half2float(hi));
}

// ---------------- K1: HMMA fp16-split GEMM 128x128 tile, split-K z=8 -------
__global__ void __launch_bounds__(256) gemm_hmma_kernel() {
    extern __shared__ __align__(128) char smem[];
    const uint32_t sb = smem_u32(smem);
    const int tid = threadIdx.x, wid = tid >> 5, lane = tid & 31;
    const int n0 = blockIdx.x * 128;
    const int m0 = blockIdx.y * 128;
    const int z  = blockIdx.z;
    const int bb = m0 / TPAD, t0 = m0 % TPAD;
    const long rowbase = (long)bb * TROWS + t0;
    const int wm = wid & 3, wn = wid >> 2;

    float c[2][8][4];    // grand accumulator
    float cc[2][8][4];   // fresh per-chunk accumulator for hh product
    #pragma unroll
    for (int i = 0; i < 2; ++i)
        #pragma unroll
        for (int j = 0; j < 8; ++j)
            #pragma unroll
            for (int v = 0; v < 4; ++v) c[i][j][v] = 0.f;

    const int frow = tid >> 1, fh = (tid & 1) * 64;   // fill row + byte-half

    auto fill = [&](int q, int s) {
        const int p = q / CPZ;
        const int k0 = z * (KTOT / ZSPLIT) + (q % CPZ) * KC;
        const int tap = k0 >> 11, f0 = k0 & 2047;
        const uint32_t base = sb + s * STAGE_BYTES;
        const char* ga = (const char*)(g_xs2 + (size_t)c_PA[p] * XT
                         + (size_t)(rowbase + tap + frow) * FDIM + f0) + fh;
        const char* gb = (const char*)(g_ws2 + (size_t)c_PB[p] * WT
                         + (size_t)(n0 + frow) * KTOT + k0) + fh;
        #pragma unroll
        for (int i = 0; i < 4; ++i) {
            uint32_t off = swz((uint32_t)(frow * 128 + fh + i * 16));
            cp16(base + off, ga + i * 16);
            cp16(base + 16384 + off, gb + i * 16);
        }
    };

    // whole-chunk mma into accumulator C
    auto domma = [&](float (&C)[2][8][4], uint32_t sA, uint32_t sB) {
        #pragma unroll
        for (int kk = 0; kk < 4; ++kk) {
            uint32_t a[2][4];
            #pragma unroll
            for (int i = 0; i < 2; ++i) {
                int r = wm * 32 + i * 16 + (lane & 15);
                int cg = kk * 2 + (lane >> 4);
                ldsm4(a[i], sA + swz((uint32_t)(r * 128 + cg * 16)));
            }
            uint32_t b[8][2];
            #pragma unroll
            for (int j = 0; j < 4; ++j) {
                int r = wn * 64 + j * 16 + (lane >> 4) * 8 + (lane & 7);
                int cg = kk * 2 + ((lane >> 3) & 1);
                uint32_t qr[4];
                ldsm4(qr, sB + swz((uint32_t)(r * 128 + cg * 16)));
                b[2 * j][0] = qr[0]; b[2 * j][1] = qr[1];
                b[2 * j + 1][0] = qr[2]; b[2 * j + 1][1] = qr[3];
            }
            #pragma unroll
            for (int i = 0; i < 2; ++i)
                #pragma unroll
                for (int j = 0; j < 8; ++j) mma16816(C[i][j], a[i], b[j]);
        }
    };

    fill(0, 0); CP_COMMIT();
    fill(1, 1); CP_COMMIT();

    for (int q = 0; q < NCHUNK; ++q) {
        if (q + 2 < NCHUNK) fill(q + 2, (q + 2) % NSTAGE);
        CP_COMMIT();
        CP_WAIT2();
        __syncthreads();   // stage q%NSTAGE fully written & visible

        const uint32_t sA = sb + (q % NSTAGE) * STAGE_BYTES;
        const uint32_t sB = sA + 16384;
        const bool fresh = (q / CPZ == NPROD - 1);   // hh product: blocked accumulation
        if (fresh) {
            #pragma unroll
            for (int i = 0; i < 2; ++i)
                #pragma unroll
                for (int j = 0; j < 8; ++j)
                    #pragma unroll
                    for (int v = 0; v < 4; ++v) cc[i][j][v] = 0.f;
            domma(cc, sA, sB);
            #pragma unroll
            for (int i = 0; i < 2; ++i)
                #pragma unroll
                for (int j = 0; j < 8; ++j)
                    #pragma unroll
                    for (int v = 0; v < 4; ++v) c[i][j][v] = __fadd_rn(c[i][j][v], cc[i][j][v]);
        } else {
            domma(c, sA, sB);
        }
        // no trailing barrier: with NSTAGE=4, the next fill targets (q+3)%4 != q%4
    }

    // epilogue -> g_part[z]
    const int grp = lane >> 2, qd = lane & 3;
    float* zbase = g_part + (size_t)z * MTOT * EMBD;
    #pragma unroll
    for (int i = 0; i < 2; ++i) {
        #pragma unroll
        for (int h = 0; h < 2; ++h) {
            int t = t0 + wm * 32 + i * 16 + grp + h * 8;
            if (t < TDIM) {
                float* dst = zbase + ((size_t)bb * TDIM + t) * EMBD + n0 + wn * 64 + qd * 2;
                #pragma unroll
                for (int j = 0; j < 8; ++j) {
                    float2 v2 = make_float2(c[i][j][h * 2], c[i][j][h * 2 + 1]);
                    *reinterpret_cast<float2*>(dst + j * 8) = v2;
                }
            }
        }
    }
}

// ---------------- K1b: combine 8 partials in double (exact) + bias + relu --
__global__ void __launch_bounds__(256) combine_kernel(const float* __restrict__ bE) {
    const size_t N4 = (size_t)MTOT * EMBD / 4;
    size_t i = (size_t)blockIdx.x * 256 + threadIdx.x;
    if (i >= N4) return;
    const float4* P = reinterpret_cast<const float4*>(g_part);
    float4 s[8];
    #pragma unroll
    for (int j = 0; j < 8; ++j) s[j] = P[i + j * N4];
    int e = (int)((i * 4) & (EMBD - 1));
    float4 b = *reinterpret_cast<const float4*>(bE + e);
    const double SC = 1.0 / 1024.0;
    float4 o;
    #define CMB(f) { double t_ = 0.0; \
        t_ += (double)s[0].f; t_ += (double)s[1].f; t_ += (double)s[2].f; t_ += (double)s[3].f; \
        t_ += (double)s[4].f; t_ += (double)s[5].f; t_ += (double)s[6].f; t_ += (double)s[7].f; \
        o.f = fmaxf((float)(t_ * SC + (double)b.f), 0.f); }
    CMB(x); CMB(y); CMB(z); CMB(w);
    #undef CMB
    reinterpret_cast<float4*>(g_emb)[i] = o;
}

// ---------------- K2: classifier + actionness ----------------
__global__ void __launch_bounds__(256) cas_kernel(const float* __restrict__ Wcls,
                                                  const float* __restrict__ bcls,
                                                  float* __restrict__ casOut) {
    __shared__ float Ws[512][21];
    const int tid = threadIdx.x, lane = tid & 31, warp = tid >> 5;
    const int row = blockIdx.x * 8 + warp;
    float acc[CDIM];
    #pragma unroll
    for (int c = 0; c < CDIM; ++c) acc[c] = 0.f;
    for (int ch = 0; ch < 4; ++ch) {
        __syncthreads();
        for (int idx = tid; idx < 512 * CDIM; idx += 256) {
            int c = idx >> 9, e = idx & 511;
            Ws[e][c] = Wcls[c * EMBD + ch * 512 + e];
        }
        __syncthreads();
        const float* er = g_emb + (size_t)row * EMBD + ch * 512;
        #pragma unroll 4
        for (int eb = 0; eb < 512; eb += 32) {
            float v = er[eb + lane];
            const float* wr = &Ws[eb + lane][0];
            #pragma unroll
            for (int c = 0; c < CDIM; ++c) acc[c] = fmaf(v, wr[c], acc[c]);
        }
    }
    double dtot = 0.0;
    float mine = 0.f;
    #pragma unroll
    for (int c = 0; c < CDIM; ++c) {
        float s = acc[c];
        #pragma unroll
        for (int o = 16; o; o >>= 1) s += __shfl_xor_sync(0xffffffffu, s, o);
        float val = __fadd_rn(s, bcls[c]);
        if (lane == c) mine = val;
        dtot += (double)val;
    }
    if (lane < CDIM) casOut[row * CDIM + lane] = mine;
    if (lane == 0)   g_a[row] = (float)dtot;
}

// ---------------- K3: circular smoothing ----------------
__global__ void smooth_kernel(float* __restrict__ actOut) {
    const int b = blockIdx.x, t = threadIdx.x;
    __shared__ float a[TDIM];
    if (t < TDIM) a[t] = g_a[b * TDIM + t];
    __syncthreads();
    if (t < TDIM) {
        int p1 = (t + 1) % TDIM,  m1 = (t + TDIM - 1) % TDIM;
        int p2 = (t + 2) % TDIM,  m2 = (t + TDIM - 2) % TDIM;
        double v = (double)a[t]
                 + 0.1  * (double)a[p1] + 0.1  * (double)a[m1]
                 + 0.02 * (double)a[p2] + 0.02 * (double)a[m2];
        float vf = (float)v;
        g_act[b * TDIM + t]  = vf;
        actOut[b * TDIM + t] = vf;
    }
}

// ---------------- bitonic sorts (blockDim = 1024) ----------------
__device__ void bitonic_f(float* d, int tid, bool desc) {
    for (int k = 2; k <= 1024; k <<= 1)
        for (int j = k >> 1; j > 0; j >>= 1) {
            int x = tid ^ j;
            if (x > tid) {
                float a = d[tid], b = d[x];
                bool up = ((tid & k) == 0) != desc;
                if (up ? (a > b) : (a < b)) { d[tid] = b; d[x] = a; }
            }
            __syncthreads();
        }
}
__device__ void bitonic_u64_desc(ull* d, int tid) {
    for (int k = 2; k <= 1024; k <<= 1)
        for (int j = k >> 1; j > 0; j >>= 1) {
            int x = tid ^ j;
            if (x > tid) {
                ull a = d[tid], b = d[x];
                bool up = ((tid & k) == 0);
                if (up ? (a < b) : (a > b)) { d[tid] = b; d[x] = a; }
            }
            __syncthreads();
        }
}

// ---------------- K4: per-batch stats + 4 index top-ks ----------------
__global__ void __launch_bounds__(1024) stats_topk_kernel() {
    const int b = blockIdx.x, tid = threadIdx.x;
    __shared__ float act[TDIM];
    __shared__ float abin[TDIM];
    __shared__ float sv[1024];
    __shared__ ull   keys[1024];
    __shared__ float scal[2];
    const float NI = __int_as_float(0xff800000);
    const float PI = __int_as_float(0x7f800000);

    if (tid < TDIM) act[tid] = g_act[b * TDIM + tid];
    __syncthreads();
    sv[tid] = (tid < TDIM) ? act[tid] : NI;
    __syncthreads();
    for (int s = 512; s > 0; s >>= 1) {
        if (tid < s) sv[tid] = fmaxf(sv[tid], sv[tid + s]);
        __syncthreads();
    }
    if (tid == 0) scal[0] = sv[0];
    __syncthreads();
    sv[tid] = (tid < TDIM) ? act[tid] : PI;
    __syncthreads();
    bitonic_f(sv, tid, false);
    if (tid == 0) scal[1] = __fmul_rn(0.5f, __fadd_rn(sv[374], sv[375]));
    __syncthreads();

    const float amax = scal[0], med = scal[1];
    if (tid < TDIM) abin[tid] = (act[tid] > med) ? 1.f : 0.f;
    __syncthreads();

    float sc[4] = {0.f, 0.f, 0.f, 0.f};
    if (tid < TDIM) {
        const int t = tid;
        const float a = act[t];
        float e3 = (t >= 1 && t <= TDIM - 2)
                       ? fminf(fminf(abin[t - 1], abin[t]), abin[t + 1]) : 0.f;
        float e6 = 0.f;
        if (t >= 3 && t <= TDIM - 3)
            e6 = fminf(fminf(fminf(abin[t - 3], abin[t - 2]), fminf(abin[t - 1], abin[t])),
                       fminf(abin[t + 1], abin[t + 2]));
        float d3 = abin[t];
        if (t >= 1)        d3 = fmaxf(d3, abin[t - 1]);
        if (t <= TDIM - 2) d3 = fmaxf(d3, abin[t + 1]);
        float d6 = abin[t];
        if (t >= 1)        d6 = fmaxf(d6, abin[t - 1]);
        if (t >= 2)        d6 = fmaxf(d6, abin[t - 2]);
        if (t <= TDIM - 2) d6 = fmaxf(d6, abin[t + 1]);
        if (t <= TDIM - 3) d6 = fmaxf(d6, abin[t + 2]);
        if (t <= TDIM - 4) d6 = fmaxf(d6, abin[t + 3]);
        sc[0] = a;
        sc[1] = __fsub_rn(amax, a);
        sc[2] = __fmul_rn(a, __fsub_rn(e3, e6));
        sc[3] = __fmul_rn(a, __fsub_rn(d6, d3));
    }

    const int kk[4]  = {KEASY, KEASY, KHARD, KHARD};
    const int off[4] = {IDX_EA, IDX_EB, IDX_HA, IDX_HB};
    for (int pass = 0; pass < 4; ++pass) {
        __syncthreads();
        ull key = 0ull;
        if (tid < TDIM) {
            unsigned u = __float_as_uint(sc[pass]);
            u = (u & 0x80000000u) ? ~u : (u | 0x80000000u);
            key = ((ull)u << 32) | (ull)(0xFFFFFFFFu - (unsigned)tid);
        }
        keys[tid] = key;
        __syncthreads();
        bitonic_u64_desc(keys, tid);
        if (tid < kk[pass]) {
            unsigned idx = 0xFFFFFFFFu - (unsigned)(keys[tid] & 0xFFFFFFFFull);
            g_idx[off[pass] + b * kk[pass] + tid] = (int)idx;
        }
    }
}

// ---------------- K5: per-(b,c) top-150 mean of cas ----------------
__global__ void __launch_bounds__(1024) classtopk_kernel(const float* __restrict__ cas) {
    const int bc = blockIdx.x;
    const int b = bc / CDIM, c = bc % CDIM;
    const int tid = threadIdx.x;
    __shared__ float sv[1024];
    sv[tid] = (tid < TDIM) ? cas[(b * TDIM + tid) * CDIM + c] : __int_as_float(0xff800000);
    __syncthreads();
    bitonic_f(sv, tid, true);
    if (tid == 0) {
        float s = 0.f;
        for (int i = 0; i < KEASY; ++i) s = __fadd_rn(s, sv[i]);
        g_vmean[bc] = s / (float)KEASY;
    }
}

// ---------------- K6: softmax ----------------
__global__ void softmax_kernel(float* __restrict__ vs) {
    const int lane = threadIdx.x & 31, w = threadIdx.x >> 5;
    if (w >= BDIM) return;
    float v = (lane < CDIM) ? g_vmean[w * CDIM + lane] : __int_as_float(0xff800000);
    float m = v;
    #pragma unroll
    for (int o = 16; o; o >>= 1) m = fmaxf(m, __shfl_xor_sync(0xffffffffu, m, o));
    float e = (lane < CDIM) ? expf(v - m) : 0.f;
    float s = e;
    #pragma unroll
    for (int o = 16; o; o >>= 1) s += __shfl_xor_sync(0xffffffffu, s, o);
    if (lane < CDIM) vs[w * CDIM + lane] = e / s;
}

// ---------------- K7: gather ----------------
__global__ void __launch_bounds__(256) gather_kernel(const int* __restrict__ idx,
                                                     int k, float* __restrict__ dst) {
    const int r = blockIdx.x;
    const int b = r / k;
    const int t = idx[r];
    const float4* src = reinterpret_cast<const float4*>(
        g_emb + (size_t)(b * TDIM + t) * EMBD);
    float4* out = reinterpret_cast<float4*>(dst + (size_t)r * EMBD);
    #pragma unroll
    for (int i = 0; i < 2; ++i)
        out[threadIdx.x + 256 * i] = src[threadIdx.x + 256 * i];
}

// ---------------- launcher ----------------
extern "C" void kernel_launch(void* const* d_in, const int* in_sizes, int n_in,
                              void* d_out, int out_size) {
    (void)in_sizes; (void)n_in; (void)out_size;
    const float* x       = (const float*)d_in[0];
    const float* W_embed = (const float*)d_in[1];
    const float* b_embed = (const float*)d_in[2];
    const float* W_cls   = (const float*)d_in[3];
    const float* b_cls   = (const float*)d_in[4];
    float* out = (float*)d_out;

    int* idxp;
    cudaGetSymbolAddress((void**)&idxp, g_idx);
    cudaFuncSetAttribute(gemm_hmma_kernel,
                         cudaFuncAttributeMaxDynamicSharedMemorySize, SM_TOTAL);

    splitx_kernel<<<(unsigned)((XT + 255) / 256), 256>>>(x);
    splitw_kernel<<<(unsigned)((WT + 255) / 256), 256>>>(W_embed);
    gemm_hmma_kernel<<<dim3(EMBD / 128, MPAD / 128, ZSPLIT), 256, SM_TOTAL>>>();
    {
        size_t n4 = (size_t)MTOT * EMBD / 4;
        combine_kernel<<<(unsigned)((n4 + 255) / 256), 256>>>(b_embed);
    }
    cas_kernel<<<MTOT / 8, 256>>>(W_cls, b_cls, out + OFF_CAS);
    smooth_kernel<<<BDIM, 768>>>(out + OFF_ACT);
    stats_topk_kernel<<<BDIM, 1024>>>();
    classtopk_kernel<<<BDIM * CDIM, 1024>>>(out + OFF_CAS);
    softmax_kernel<<<1, 1024>>>(out + OFF_VS);
    gather_kernel<<<BDIM * KEASY, 256>>>(idxp + IDX_EA, KEASY, out + OFF_EA);
    gather_kernel<<<BDIM * KEASY, 256>>>(idxp + IDX_EB, KEASY, out + OFF_EB);
    gather_kernel<<<BDIM * KHARD, 256>>>(idxp + IDX_HA, KHARD, out + OFF_HA);
    gather_kernel<<<BDIM * KHARD, 256>>>(idxp + IDX_HB, KHARD, out + OFF_HB);
}